// round 9
// baseline (speedup 1.0000x reference)
#include <cuda_runtime.h>
#include <cstdint>

// Batched 256-point complex DFT, out = FFT(x) / sqrt(256).
// Four-step: 256 = 16 x 16. 16 threads/frame, 4 frames per 64-thread block,
// TWO frame-groups per block:
//   group 0: front-batched LDG.32 into registers (critical path, deep MLP)
//   group 1: cp.async.cg 16B into padded shared staging -> zero register
//            cost while in flight (R7 showed reg-resident prefetch caps
//            occupancy at 22%; this keeps the overlap AND the warps)
// W16 twiddles immediates; W256^{t*k}/16 via register power tree (reused by
// both groups). Transpose via padded float2 shared, __syncwarp only.

#define NPT      256
#define FPB      4
#define BLOCK    64
#define ROWS     17                 // padded row stride, float2 units
#define FS2      (16 * ROWS)        // transpose frame stride, float2 (272)
#define STF      272                // staging frame stride, floats (272%32==16)

__device__ __forceinline__ void cpasync16(unsigned int dst, const float* src)
{
    asm volatile("cp.async.cg.shared.global [%0], [%1], 16;"
                 :: "r"(dst), "l"(src) : "memory");
}

__device__ __forceinline__ float2 cmul(float2 a, float2 b)
{
    return make_float2(a.x * b.x - a.y * b.y,
                       a.x * b.y + a.y * b.x);
}

__device__ __forceinline__ void dft4(
    float& r0, float& i0, float& r1, float& i1,
    float& r2, float& i2, float& r3, float& i3)
{
    float t0r = r0 + r2, t0i = i0 + i2;
    float t1r = r0 - r2, t1i = i0 - i2;
    float t2r = r1 + r3, t2i = i1 + i3;
    float t3r = r1 - r3, t3i = i1 - i3;
    r0 = t0r + t2r;  i0 = t0i + t2i;
    r2 = t0r - t2r;  i2 = t0i - t2i;
    r1 = t1r + t3i;  i1 = t1i - t3r;   // t1 - i*t3
    r3 = t1r - t3i;  i3 = t1i + t3r;   // t1 + i*t3
}

// In-register forward 16-pt DFT (two radix-4 stages, DIT).
// Output X[4*k1+k2] lives in slot (4*k2+k1); callers remap with rev4().
__device__ __forceinline__ void fft16(float* xr, float* xi)
{
    constexpr float WR[10] = {
        1.f,  0.92387953251128674f,  0.70710678118654752f,  0.38268343236508977f,
        0.f, -0.38268343236508977f, -0.70710678118654752f, -0.92387953251128674f,
       -1.f, -0.92387953251128674f };
    constexpr float WI[10] = {
        0.f, -0.38268343236508977f, -0.70710678118654752f, -0.92387953251128674f,
       -1.f, -0.92387953251128674f, -0.70710678118654752f, -0.38268343236508977f,
        0.f,  0.38268343236508977f };

#pragma unroll
    for (int n1 = 0; n1 < 4; n1++) {
        dft4(xr[n1],    xi[n1],
             xr[n1+4],  xi[n1+4],
             xr[n1+8],  xi[n1+8],
             xr[n1+12], xi[n1+12]);
    }
#pragma unroll
    for (int n1 = 1; n1 < 4; n1++) {
#pragma unroll
        for (int k2 = 1; k2 < 4; k2++) {
            int s = n1 + 4 * k2;
            int m = n1 * k2;               // 1..9
            float wr = WR[m], wi = WI[m];
            float ar = xr[s], ai = xi[s];
            xr[s] = ar * wr - ai * wi;
            xi[s] = ar * wi + ai * wr;
        }
    }
#pragma unroll
    for (int k2 = 0; k2 < 4; k2++) {
        dft4(xr[4*k2+0], xi[4*k2+0],
             xr[4*k2+1], xi[4*k2+1],
             xr[4*k2+2], xi[4*k2+2],
             xr[4*k2+3], xi[4*k2+3]);
    }
}

__device__ __forceinline__ int rev4(int k) { return ((k & 3) << 2) | (k >> 2); }

// FFT + twiddle + transpose + second FFT + stores for one frame.
__device__ __forceinline__ void process_frame(
    float* ar, float* ai, float2* s, int t,
    const float2* Q, const float2* L,
    float* __restrict__ orp, float* __restrict__ oip)
{
    fft16(ar, ai);

#pragma unroll
    for (int k = 0; k < 16; k++) {
        int sl = rev4(k);
        float2 wk = cmul(Q[k >> 2], L[k & 3]);
        float2 v  = make_float2(ar[sl], ai[sl]);
        s[k * ROWS + t] = cmul(v, wk);
    }
    __syncwarp();                        // transpose is intra-warp

    float br[16], bi[16];
#pragma unroll
    for (int n1 = 0; n1 < 16; n1++) {
        float2 v = s[t * ROWS + n1];
        br[n1] = v.x;  bi[n1] = v.y;
    }
    __syncwarp();                        // WAR guard: buffer reused next group
    fft16(br, bi);

#pragma unroll
    for (int k1 = 0; k1 < 16; k1++) {
        int sl = rev4(k1);
        __stcs(orp + k1 * 16 + t, br[sl]);
        __stcs(oip + k1 * 16 + t, bi[sl]);
    }
}

__global__ void __launch_bounds__(BLOCK)
dft256_kernel(const float* __restrict__ xr, const float* __restrict__ xi,
              const float* __restrict__ Wr, const float* __restrict__ Wi,
              float* __restrict__ outR, float* __restrict__ outI)
{
    __shared__ float  stR[FPB * STF], stI[FPB * STF];  // group-1 staging
    __shared__ float2 sh[FPB * FS2];                   // transpose buffer

    const int tid = threadIdx.x;
    const int f = tid >> 4;              // frame within group
    const int t = tid & 15;              // lane within frame

    const size_t frame0 = ((size_t)blockIdx.x * 2) * FPB + f;  // group 0
    const size_t frame1 = frame0 + FPB;                        // group 1
    const float* xr0 = xr + frame0 * NPT;
    const float* xi0 = xi + frame0 * NPT;
    const float* xr1 = xr + frame1 * NPT;
    const float* xi1 = xi + frame1 * NPT;

    // ---- group 0: front-batched register loads (critical path) ----
    float ar[16], ai[16];
#pragma unroll
    for (int n2 = 0; n2 < 16; n2++) {
        ar[n2] = __ldcs(xr0 + n2 * 16 + t);
        ai[n2] = __ldcs(xi0 + n2 * 16 + t);
    }

    // ---- group 1: cp.async 16B prefetch into shared (no registers held) ----
    {
        unsigned int dR = (unsigned int)__cvta_generic_to_shared(&stR[f * STF]);
        unsigned int dI = (unsigned int)__cvta_generic_to_shared(&stI[f * STF]);
#pragma unroll
        for (int j = 0; j < 4; j++) {
            int c = t + 16 * j;          // float4 chunk index within frame
            cpasync16(dR + 16 * c, xr1 + 4 * c);
            cpasync16(dI + 16 * c, xi1 + 4 * c);
        }
        asm volatile("cp.async.commit_group;" ::: "memory");
    }

    // ---- step-2 twiddles in registers (shared by both groups) ----
    float2 w1 = make_float2(Wr[NPT + t], Wi[NPT + t]);   // W256^t
    float2 w2 = cmul(w1, w1);
    float2 w3 = cmul(w2, w1);
    float2 w4 = cmul(w2, w2);
    float2 w8 = cmul(w4, w4);
    float2 L[4] = { make_float2(1.f, 0.f), w1, w2, w3 };
    float2 Q[4];
    Q[0] = make_float2(0.0625f, 0.f);
    Q[1] = make_float2(0.0625f * w4.x, 0.0625f * w4.y);
    Q[2] = make_float2(0.0625f * w8.x, 0.0625f * w8.y);
    Q[3] = cmul(Q[2], w4);               // w12 / 16

    float2* s = sh + f * FS2;

    // ---- group 0: compute + store while group 1 streams into shared ----
    process_frame(ar, ai, s, t, Q, L,
                  outR + frame0 * NPT, outI + frame0 * NPT);

    // ---- group 1: drain prefetch, strided conflict-free LDS, process ----
    asm volatile("cp.async.wait_group 0;" ::: "memory");
    __syncwarp();                        // chunks written by other lanes

    float cr[16], ci[16];
    const float* sR = &stR[f * STF];
    const float* sI = &stI[f * STF];
#pragma unroll
    for (int n2 = 0; n2 < 16; n2++) {
        cr[n2] = sR[n2 * 16 + t];
        ci[n2] = sI[n2 * 16 + t];
    }
    process_frame(cr, ci, s, t, Q, L,
                  outR + frame1 * NPT, outI + frame1 * NPT);
}

extern "C" void kernel_launch(void* const* d_in, const int* in_sizes, int n_in,
                              void* d_out, int out_size)
{
    const float* x_real = (const float*)d_in[0];
    const float* x_imag = (const float*)d_in[1];
    const float* W_real = (const float*)d_in[2];
    const float* W_imag = (const float*)d_in[3];

    const size_t nframes = (size_t)in_sizes[0] / NPT;   // 262144
    float* outR = (float*)d_out;
    float* outI = outR + nframes * NPT;                 // [real | imag]

    const int grid = (int)(nframes / (FPB * 2));        // 32768
    dft256_kernel<<<grid, BLOCK>>>(x_real, x_imag, W_real, W_imag, outR, outI);
}

// round 10
// speedup vs baseline: 1.1088x; 1.1088x over previous
#include <cuda_runtime.h>

// Batched 256-point complex DFT, out = FFT(x) / sqrt(256).
// Four-step: 256 = 16 x 16. 16 threads/frame, 4 frames per 64-thread block,
// TWO frame-groups per block, register double-buffered (R7 structure: deep
// per-warp MLP beats occupancy on this chip; cp.async variant regressed).
// R10 deltas vs R7:
//   - loads grouped per input array (xr0 | xi0 | xr1 | xi1): each 16-load
//     batch covers one contiguous 1KB region -> better DRAM row locality
//   - stores split per output plane for the same reason
//   - __launch_bounds__(64, 10): gentle reg cap (108 -> <=102) for 10 CTA/SM
// W16 twiddles immediates; W256^{t*k}/16 via register power tree.
// Transpose via padded float2 shared, __syncwarp only (no block barriers).

#define NPT      256
#define FPB      4
#define BLOCK    64
#define ROWS     17                 // padded row stride, float2 units
#define FS2      (16 * ROWS)        // frame stride, float2 units (272)

__device__ __forceinline__ float2 cmul(float2 a, float2 b)
{
    return make_float2(a.x * b.x - a.y * b.y,
                       a.x * b.y + a.y * b.x);
}

__device__ __forceinline__ void dft4(
    float& r0, float& i0, float& r1, float& i1,
    float& r2, float& i2, float& r3, float& i3)
{
    float t0r = r0 + r2, t0i = i0 + i2;
    float t1r = r0 - r2, t1i = i0 - i2;
    float t2r = r1 + r3, t2i = i1 + i3;
    float t3r = r1 - r3, t3i = i1 - i3;
    r0 = t0r + t2r;  i0 = t0i + t2i;
    r2 = t0r - t2r;  i2 = t0i - t2i;
    r1 = t1r + t3i;  i1 = t1i - t3r;   // t1 - i*t3
    r3 = t1r - t3i;  i3 = t1i + t3r;   // t1 + i*t3
}

// In-register forward 16-pt DFT (two radix-4 stages, DIT).
// Output X[4*k1+k2] lives in slot (4*k2+k1); callers remap with rev4().
__device__ __forceinline__ void fft16(float* xr, float* xi)
{
    constexpr float WR[10] = {
        1.f,  0.92387953251128674f,  0.70710678118654752f,  0.38268343236508977f,
        0.f, -0.38268343236508977f, -0.70710678118654752f, -0.92387953251128674f,
       -1.f, -0.92387953251128674f };
    constexpr float WI[10] = {
        0.f, -0.38268343236508977f, -0.70710678118654752f, -0.92387953251128674f,
       -1.f, -0.92387953251128674f, -0.70710678118654752f, -0.38268343236508977f,
        0.f,  0.38268343236508977f };

#pragma unroll
    for (int n1 = 0; n1 < 4; n1++) {
        dft4(xr[n1],    xi[n1],
             xr[n1+4],  xi[n1+4],
             xr[n1+8],  xi[n1+8],
             xr[n1+12], xi[n1+12]);
    }
#pragma unroll
    for (int n1 = 1; n1 < 4; n1++) {
#pragma unroll
        for (int k2 = 1; k2 < 4; k2++) {
            int s = n1 + 4 * k2;
            int m = n1 * k2;               // 1..9
            float wr = WR[m], wi = WI[m];
            float ar = xr[s], ai = xi[s];
            xr[s] = ar * wr - ai * wi;
            xi[s] = ar * wi + ai * wr;
        }
    }
#pragma unroll
    for (int k2 = 0; k2 < 4; k2++) {
        dft4(xr[4*k2+0], xi[4*k2+0],
             xr[4*k2+1], xi[4*k2+1],
             xr[4*k2+2], xi[4*k2+2],
             xr[4*k2+3], xi[4*k2+3]);
    }
}

__device__ __forceinline__ int rev4(int k) { return ((k & 3) << 2) | (k >> 2); }

// FFT + twiddle + transpose + second FFT + stores for one frame.
__device__ __forceinline__ void process_frame(
    float* ar, float* ai, float2* s, int t,
    const float2* Q, const float2* L,
    float* __restrict__ orp, float* __restrict__ oip)
{
    fft16(ar, ai);

#pragma unroll
    for (int k = 0; k < 16; k++) {
        int sl = rev4(k);
        float2 wk = cmul(Q[k >> 2], L[k & 3]);
        float2 v  = make_float2(ar[sl], ai[sl]);
        s[k * ROWS + t] = cmul(v, wk);
    }
    __syncwarp();                        // transpose is intra-warp

    float br[16], bi[16];
#pragma unroll
    for (int n1 = 0; n1 < 16; n1++) {
        float2 v = s[t * ROWS + n1];
        br[n1] = v.x;  bi[n1] = v.y;
    }
    __syncwarp();                        // WAR guard: buffer reused next group
    fft16(br, bi);

    // stores split per plane: each 16-store run stays in one 1KB region
#pragma unroll
    for (int k1 = 0; k1 < 16; k1++) {
        __stcs(orp + k1 * 16 + t, br[rev4(k1)]);
    }
#pragma unroll
    for (int k1 = 0; k1 < 16; k1++) {
        __stcs(oip + k1 * 16 + t, bi[rev4(k1)]);
    }
}

__global__ void __launch_bounds__(BLOCK, 10)
dft256_kernel(const float* __restrict__ xr, const float* __restrict__ xi,
              const float* __restrict__ Wr, const float* __restrict__ Wi,
              float* __restrict__ outR, float* __restrict__ outI)
{
    __shared__ float2 sh[FPB * FS2];     // transpose buffer (reused per group)

    const int tid = threadIdx.x;
    const int f = tid >> 4;              // frame within group
    const int t = tid & 15;              // lane within frame (half-warp local)

    const size_t frame0 = ((size_t)blockIdx.x * 2) * FPB + f;   // group 0
    const size_t frame1 = frame0 + FPB;                         // group 1
    const float* xr0 = xr + frame0 * NPT;
    const float* xi0 = xi + frame0 * NPT;
    const float* xr1 = xr + frame1 * NPT;
    const float* xi1 = xi + frame1 * NPT;

    // ---- front-batch BOTH groups' loads, grouped per array (row locality) ----
    float ar[16], ai[16], cr[16], ci[16];
#pragma unroll
    for (int n2 = 0; n2 < 16; n2++) ar[n2] = __ldcs(xr0 + n2 * 16 + t);
#pragma unroll
    for (int n2 = 0; n2 < 16; n2++) ai[n2] = __ldcs(xi0 + n2 * 16 + t);
#pragma unroll
    for (int n2 = 0; n2 < 16; n2++) cr[n2] = __ldcs(xr1 + n2 * 16 + t);
#pragma unroll
    for (int n2 = 0; n2 < 16; n2++) ci[n2] = __ldcs(xi1 + n2 * 16 + t);

    // ---- step-2 twiddles in registers (shared by both groups) ----
    float2 w1 = make_float2(Wr[NPT + t], Wi[NPT + t]);   // W256^t
    float2 w2 = cmul(w1, w1);
    float2 w3 = cmul(w2, w1);
    float2 w4 = cmul(w2, w2);
    float2 w8 = cmul(w4, w4);
    float2 L[4] = { make_float2(1.f, 0.f), w1, w2, w3 };
    float2 Q[4];
    Q[0] = make_float2(0.0625f, 0.f);
    Q[1] = make_float2(0.0625f * w4.x, 0.0625f * w4.y);
    Q[2] = make_float2(0.0625f * w8.x, 0.0625f * w8.y);
    Q[3] = cmul(Q[2], w4);               // w12 / 16

    float2* s = sh + f * FS2;

    // ---- group 0: compute + store while group 1 loads are in flight ----
    process_frame(ar, ai, s, t, Q, L,
                  outR + frame0 * NPT, outI + frame0 * NPT);

    // ---- group 1 ----
    process_frame(cr, ci, s, t, Q, L,
                  outR + frame1 * NPT, outI + frame1 * NPT);
}

extern "C" void kernel_launch(void* const* d_in, const int* in_sizes, int n_in,
                              void* d_out, int out_size)
{
    const float* x_real = (const float*)d_in[0];
    const float* x_imag = (const float*)d_in[1];
    const float* W_real = (const float*)d_in[2];
    const float* W_imag = (const float*)d_in[3];

    const size_t nframes = (size_t)in_sizes[0] / NPT;   // 262144
    float* outR = (float*)d_out;
    float* outI = outR + nframes * NPT;                 // [real | imag]

    const int grid = (int)(nframes / (FPB * 2));        // 32768
    dft256_kernel<<<grid, BLOCK>>>(x_real, x_imag, W_real, W_imag, outR, outI);
}

// round 11
// speedup vs baseline: 1.1284x; 1.0177x over previous
#include <cuda_runtime.h>

// Batched 256-point complex DFT, out = FFT(x) / sqrt(256).
// Four-step: 256 = 16 x 16. 16 threads/frame, 4 frames per 64-thread block,
// TWO frame-groups per block, register double-buffered (R7 structure).
// R11 = R7 + per-array load batching + per-plane store splitting ONLY.
// NO register cap: R4/R9/R10 all showed that squeezing registers breaks the
// front-batched load window (MLP) and costs more than occupancy repays.
// W16 twiddles immediates; W256^{t*k}/16 via register power tree.
// Transpose via padded float2 shared, __syncwarp only (no block barriers).

#define NPT      256
#define FPB      4
#define BLOCK    64
#define ROWS     17                 // padded row stride, float2 units
#define FS2      (16 * ROWS)        // frame stride, float2 units (272)

__device__ __forceinline__ float2 cmul(float2 a, float2 b)
{
    return make_float2(a.x * b.x - a.y * b.y,
                       a.x * b.y + a.y * b.x);
}

__device__ __forceinline__ void dft4(
    float& r0, float& i0, float& r1, float& i1,
    float& r2, float& i2, float& r3, float& i3)
{
    float t0r = r0 + r2, t0i = i0 + i2;
    float t1r = r0 - r2, t1i = i0 - i2;
    float t2r = r1 + r3, t2i = i1 + i3;
    float t3r = r1 - r3, t3i = i1 - i3;
    r0 = t0r + t2r;  i0 = t0i + t2i;
    r2 = t0r - t2r;  i2 = t0i - t2i;
    r1 = t1r + t3i;  i1 = t1i - t3r;   // t1 - i*t3
    r3 = t1r - t3i;  i3 = t1i + t3r;   // t1 + i*t3
}

// In-register forward 16-pt DFT (two radix-4 stages, DIT).
// Output X[4*k1+k2] lives in slot (4*k2+k1); callers remap with rev4().
__device__ __forceinline__ void fft16(float* xr, float* xi)
{
    constexpr float WR[10] = {
        1.f,  0.92387953251128674f,  0.70710678118654752f,  0.38268343236508977f,
        0.f, -0.38268343236508977f, -0.70710678118654752f, -0.92387953251128674f,
       -1.f, -0.92387953251128674f };
    constexpr float WI[10] = {
        0.f, -0.38268343236508977f, -0.70710678118654752f, -0.92387953251128674f,
       -1.f, -0.92387953251128674f, -0.70710678118654752f, -0.38268343236508977f,
        0.f,  0.38268343236508977f };

#pragma unroll
    for (int n1 = 0; n1 < 4; n1++) {
        dft4(xr[n1],    xi[n1],
             xr[n1+4],  xi[n1+4],
             xr[n1+8],  xi[n1+8],
             xr[n1+12], xi[n1+12]);
    }
#pragma unroll
    for (int n1 = 1; n1 < 4; n1++) {
#pragma unroll
        for (int k2 = 1; k2 < 4; k2++) {
            int s = n1 + 4 * k2;
            int m = n1 * k2;               // 1..9
            float wr = WR[m], wi = WI[m];
            float ar = xr[s], ai = xi[s];
            xr[s] = ar * wr - ai * wi;
            xi[s] = ar * wi + ai * wr;
        }
    }
#pragma unroll
    for (int k2 = 0; k2 < 4; k2++) {
        dft4(xr[4*k2+0], xi[4*k2+0],
             xr[4*k2+1], xi[4*k2+1],
             xr[4*k2+2], xi[4*k2+2],
             xr[4*k2+3], xi[4*k2+3]);
    }
}

__device__ __forceinline__ int rev4(int k) { return ((k & 3) << 2) | (k >> 2); }

// FFT + twiddle + transpose + second FFT + stores for one frame.
__device__ __forceinline__ void process_frame(
    float* ar, float* ai, float2* s, int t,
    const float2* Q, const float2* L,
    float* __restrict__ orp, float* __restrict__ oip)
{
    fft16(ar, ai);

#pragma unroll
    for (int k = 0; k < 16; k++) {
        int sl = rev4(k);
        float2 wk = cmul(Q[k >> 2], L[k & 3]);
        float2 v  = make_float2(ar[sl], ai[sl]);
        s[k * ROWS + t] = cmul(v, wk);
    }
    __syncwarp();                        // transpose is intra-warp

    float br[16], bi[16];
#pragma unroll
    for (int n1 = 0; n1 < 16; n1++) {
        float2 v = s[t * ROWS + n1];
        br[n1] = v.x;  bi[n1] = v.y;
    }
    __syncwarp();                        // WAR guard: buffer reused next group
    fft16(br, bi);

    // stores split per plane: each 16-store run stays in one 1KB region
#pragma unroll
    for (int k1 = 0; k1 < 16; k1++) {
        __stcs(orp + k1 * 16 + t, br[rev4(k1)]);
    }
#pragma unroll
    for (int k1 = 0; k1 < 16; k1++) {
        __stcs(oip + k1 * 16 + t, bi[rev4(k1)]);
    }
}

__global__ void __launch_bounds__(BLOCK)
dft256_kernel(const float* __restrict__ xr, const float* __restrict__ xi,
              const float* __restrict__ Wr, const float* __restrict__ Wi,
              float* __restrict__ outR, float* __restrict__ outI)
{
    __shared__ float2 sh[FPB * FS2];     // transpose buffer (reused per group)

    const int tid = threadIdx.x;
    const int f = tid >> 4;              // frame within group
    const int t = tid & 15;              // lane within frame (half-warp local)

    const size_t frame0 = ((size_t)blockIdx.x * 2) * FPB + f;   // group 0
    const size_t frame1 = frame0 + FPB;                         // group 1
    const float* xr0 = xr + frame0 * NPT;
    const float* xi0 = xi + frame0 * NPT;
    const float* xr1 = xr + frame1 * NPT;
    const float* xi1 = xi + frame1 * NPT;

    // ---- front-batch BOTH groups' loads, grouped per array (row locality) ----
    float ar[16], ai[16], cr[16], ci[16];
#pragma unroll
    for (int n2 = 0; n2 < 16; n2++) ar[n2] = __ldcs(xr0 + n2 * 16 + t);
#pragma unroll
    for (int n2 = 0; n2 < 16; n2++) ai[n2] = __ldcs(xi0 + n2 * 16 + t);
#pragma unroll
    for (int n2 = 0; n2 < 16; n2++) cr[n2] = __ldcs(xr1 + n2 * 16 + t);
#pragma unroll
    for (int n2 = 0; n2 < 16; n2++) ci[n2] = __ldcs(xi1 + n2 * 16 + t);

    // ---- step-2 twiddles in registers (shared by both groups) ----
    float2 w1 = make_float2(Wr[NPT + t], Wi[NPT + t]);   // W256^t
    float2 w2 = cmul(w1, w1);
    float2 w3 = cmul(w2, w1);
    float2 w4 = cmul(w2, w2);
    float2 w8 = cmul(w4, w4);
    float2 L[4] = { make_float2(1.f, 0.f), w1, w2, w3 };
    float2 Q[4];
    Q[0] = make_float2(0.0625f, 0.f);
    Q[1] = make_float2(0.0625f * w4.x, 0.0625f * w4.y);
    Q[2] = make_float2(0.0625f * w8.x, 0.0625f * w8.y);
    Q[3] = cmul(Q[2], w4);               // w12 / 16

    float2* s = sh + f * FS2;

    // ---- group 0: compute + store while group 1 loads are in flight ----
    process_frame(ar, ai, s, t, Q, L,
                  outR + frame0 * NPT, outI + frame0 * NPT);

    // ---- group 1 ----
    process_frame(cr, ci, s, t, Q, L,
                  outR + frame1 * NPT, outI + frame1 * NPT);
}

extern "C" void kernel_launch(void* const* d_in, const int* in_sizes, int n_in,
                              void* d_out, int out_size)
{
    const float* x_real = (const float*)d_in[0];
    const float* x_imag = (const float*)d_in[1];
    const float* W_real = (const float*)d_in[2];
    const float* W_imag = (const float*)d_in[3];

    const size_t nframes = (size_t)in_sizes[0] / NPT;   // 262144
    float* outR = (float*)d_out;
    float* outI = outR + nframes * NPT;                 // [real | imag]

    const int grid = (int)(nframes / (FPB * 2));        // 32768
    dft256_kernel<<<grid, BLOCK>>>(x_real, x_imag, W_real, W_imag, outR, outI);
}

// round 12
// speedup vs baseline: 1.1289x; 1.0004x over previous
#include <cuda_runtime.h>

// Batched 256-point complex DFT, out = FFT(x) / sqrt(256).
// Four-step: 256 = 16 x 16. 16 threads/frame, 4 frames per 64-thread block,
// TWO frame-groups per block, register double-buffered.
// R12 delta vs R11: group-1's imag-plane loads are issued AFTER the first
// fft16 instead of at the very front. This trims peak register liveness by
// ~16 (compiler-chosen, NOT launch_bounds-capped — caps regressed in
// R4/R10) while keeping >=48 outstanding loads at the front and refilling
// the memory pipe mid-stream. Per-array load batching + per-plane store
// splitting retained (DRAM row locality, R11 win).
// W16 twiddles immediates; W256^{t*k}/16 via register power tree.
// Transpose via padded float2 shared, __syncwarp only (no block barriers).

#define NPT      256
#define FPB      4
#define BLOCK    64
#define ROWS     17                 // padded row stride, float2 units
#define FS2      (16 * ROWS)        // frame stride, float2 units (272)

__device__ __forceinline__ float2 cmul(float2 a, float2 b)
{
    return make_float2(a.x * b.x - a.y * b.y,
                       a.x * b.y + a.y * b.x);
}

__device__ __forceinline__ void dft4(
    float& r0, float& i0, float& r1, float& i1,
    float& r2, float& i2, float& r3, float& i3)
{
    float t0r = r0 + r2, t0i = i0 + i2;
    float t1r = r0 - r2, t1i = i0 - i2;
    float t2r = r1 + r3, t2i = i1 + i3;
    float t3r = r1 - r3, t3i = i1 - i3;
    r0 = t0r + t2r;  i0 = t0i + t2i;
    r2 = t0r - t2r;  i2 = t0i - t2i;
    r1 = t1r + t3i;  i1 = t1i - t3r;   // t1 - i*t3
    r3 = t1r - t3i;  i3 = t1i + t3r;   // t1 + i*t3
}

// In-register forward 16-pt DFT (two radix-4 stages, DIT).
// Output X[4*k1+k2] lives in slot (4*k2+k1); callers remap with rev4().
__device__ __forceinline__ void fft16(float* xr, float* xi)
{
    constexpr float WR[10] = {
        1.f,  0.92387953251128674f,  0.70710678118654752f,  0.38268343236508977f,
        0.f, -0.38268343236508977f, -0.70710678118654752f, -0.92387953251128674f,
       -1.f, -0.92387953251128674f };
    constexpr float WI[10] = {
        0.f, -0.38268343236508977f, -0.70710678118654752f, -0.92387953251128674f,
       -1.f, -0.92387953251128674f, -0.70710678118654752f, -0.38268343236508977f,
        0.f,  0.38268343236508977f };

#pragma unroll
    for (int n1 = 0; n1 < 4; n1++) {
        dft4(xr[n1],    xi[n1],
             xr[n1+4],  xi[n1+4],
             xr[n1+8],  xi[n1+8],
             xr[n1+12], xi[n1+12]);
    }
#pragma unroll
    for (int n1 = 1; n1 < 4; n1++) {
#pragma unroll
        for (int k2 = 1; k2 < 4; k2++) {
            int s = n1 + 4 * k2;
            int m = n1 * k2;               // 1..9
            float wr = WR[m], wi = WI[m];
            float ar = xr[s], ai = xi[s];
            xr[s] = ar * wr - ai * wi;
            xi[s] = ar * wi + ai * wr;
        }
    }
#pragma unroll
    for (int k2 = 0; k2 < 4; k2++) {
        dft4(xr[4*k2+0], xi[4*k2+0],
             xr[4*k2+1], xi[4*k2+1],
             xr[4*k2+2], xi[4*k2+2],
             xr[4*k2+3], xi[4*k2+3]);
    }
}

__device__ __forceinline__ int rev4(int k) { return ((k & 3) << 2) | (k >> 2); }

// FFT + twiddle + transpose + second FFT + stores for one frame.
__device__ __forceinline__ void process_frame(
    float* ar, float* ai, float2* s, int t,
    const float2* Q, const float2* L,
    float* __restrict__ orp, float* __restrict__ oip)
{
    fft16(ar, ai);

#pragma unroll
    for (int k = 0; k < 16; k++) {
        int sl = rev4(k);
        float2 wk = cmul(Q[k >> 2], L[k & 3]);
        float2 v  = make_float2(ar[sl], ai[sl]);
        s[k * ROWS + t] = cmul(v, wk);
    }
    __syncwarp();                        // transpose is intra-warp

    float br[16], bi[16];
#pragma unroll
    for (int n1 = 0; n1 < 16; n1++) {
        float2 v = s[t * ROWS + n1];
        br[n1] = v.x;  bi[n1] = v.y;
    }
    __syncwarp();                        // WAR guard: buffer reused next group
    fft16(br, bi);

    // stores split per plane: each 16-store run stays in one 1KB region
#pragma unroll
    for (int k1 = 0; k1 < 16; k1++) {
        __stcs(orp + k1 * 16 + t, br[rev4(k1)]);
    }
#pragma unroll
    for (int k1 = 0; k1 < 16; k1++) {
        __stcs(oip + k1 * 16 + t, bi[rev4(k1)]);
    }
}

__global__ void __launch_bounds__(BLOCK)
dft256_kernel(const float* __restrict__ xr, const float* __restrict__ xi,
              const float* __restrict__ Wr, const float* __restrict__ Wi,
              float* __restrict__ outR, float* __restrict__ outI)
{
    __shared__ float2 sh[FPB * FS2];     // transpose buffer (reused per group)

    const int tid = threadIdx.x;
    const int f = tid >> 4;              // frame within group
    const int t = tid & 15;              // lane within frame (half-warp local)

    const size_t frame0 = ((size_t)blockIdx.x * 2) * FPB + f;   // group 0
    const size_t frame1 = frame0 + FPB;                         // group 1
    const float* xr0 = xr + frame0 * NPT;
    const float* xi0 = xi + frame0 * NPT;
    const float* xr1 = xr + frame1 * NPT;
    const float* xi1 = xi + frame1 * NPT;

    // ---- front batch: group 0 (both planes) + group 1 real plane ----
    float ar[16], ai[16], cr[16], ci[16];
#pragma unroll
    for (int n2 = 0; n2 < 16; n2++) ar[n2] = __ldcs(xr0 + n2 * 16 + t);
#pragma unroll
    for (int n2 = 0; n2 < 16; n2++) ai[n2] = __ldcs(xi0 + n2 * 16 + t);
#pragma unroll
    for (int n2 = 0; n2 < 16; n2++) cr[n2] = __ldcs(xr1 + n2 * 16 + t);

    // ---- step-2 twiddles in registers (shared by both groups) ----
    float2 w1 = make_float2(Wr[NPT + t], Wi[NPT + t]);   // W256^t
    float2 w2 = cmul(w1, w1);
    float2 w3 = cmul(w2, w1);
    float2 w4 = cmul(w2, w2);
    float2 w8 = cmul(w4, w4);
    float2 L[4] = { make_float2(1.f, 0.f), w1, w2, w3 };
    float2 Q[4];
    Q[0] = make_float2(0.0625f, 0.f);
    Q[1] = make_float2(0.0625f * w4.x, 0.0625f * w4.y);
    Q[2] = make_float2(0.0625f * w8.x, 0.0625f * w8.y);
    Q[3] = cmul(Q[2], w4);               // w12 / 16

    float2* s = sh + f * FS2;

    // ---- group 0 step 1 ----
    fft16(ar, ai);

    // ---- staggered refill: group 1 imag plane issued here, overlapping
    //      group 0's transpose + second FFT + stores ----
#pragma unroll
    for (int n2 = 0; n2 < 16; n2++) ci[n2] = __ldcs(xi1 + n2 * 16 + t);

    // ---- group 0 steps 2-4 ----
#pragma unroll
    for (int k = 0; k < 16; k++) {
        int sl = rev4(k);
        float2 wk = cmul(Q[k >> 2], L[k & 3]);
        float2 v  = make_float2(ar[sl], ai[sl]);
        s[k * ROWS + t] = cmul(v, wk);
    }
    __syncwarp();

    {
        float br[16], bi[16];
#pragma unroll
        for (int n1 = 0; n1 < 16; n1++) {
            float2 v = s[t * ROWS + n1];
            br[n1] = v.x;  bi[n1] = v.y;
        }
        __syncwarp();                    // WAR guard before group 1 reuses sh
        fft16(br, bi);

        float* orp = outR + frame0 * NPT;
        float* oip = outI + frame0 * NPT;
#pragma unroll
        for (int k1 = 0; k1 < 16; k1++) {
            __stcs(orp + k1 * 16 + t, br[rev4(k1)]);
        }
#pragma unroll
        for (int k1 = 0; k1 < 16; k1++) {
            __stcs(oip + k1 * 16 + t, bi[rev4(k1)]);
        }
    }

    // ---- group 1 ----
    process_frame(cr, ci, s, t, Q, L,
                  outR + frame1 * NPT, outI + frame1 * NPT);
}

extern "C" void kernel_launch(void* const* d_in, const int* in_sizes, int n_in,
                              void* d_out, int out_size)
{
    const float* x_real = (const float*)d_in[0];
    const float* x_imag = (const float*)d_in[1];
    const float* W_real = (const float*)d_in[2];
    const float* W_imag = (const float*)d_in[3];

    const size_t nframes = (size_t)in_sizes[0] / NPT;   // 262144
    float* outR = (float*)d_out;
    float* outI = outR + nframes * NPT;                 // [real | imag]

    const int grid = (int)(nframes / (FPB * 2));        // 32768
    dft256_kernel<<<grid, BLOCK>>>(x_real, x_imag, W_real, W_imag, outR, outI);
}